// round 6
// baseline (speedup 1.0000x reference)
#include <cuda_runtime.h>

#define SQ      32
#define EMB     1024
#define NH      16
#define HD      64
#define PASTN   32768
#define TOT     32800
#define PCHUNK  304
#define NSPLITS 109      // 108 past splits (304 keys, last=240) + 1 new-token split
#define NSPAD   112
#define KCH     8
#define KCHLEN  128

// Scratch (allocation-free rule: __device__ globals)
__device__ float g_qkv [SQ * 3 * EMB];
__device__ float g_po  [NH * NSPLITS * SQ * HD];
__device__ float g_pml [NH * NSPLITS * SQ * 2];
__device__ float g_a   [SQ * EMB];
__device__ float g_pqkv[KCH * SQ * 3 * EMB];
__device__ float g_pprj[KCH * SQ * EMB];

// ------------------------- packed f32x2 helpers ----------------------------
__device__ __forceinline__ unsigned long long ffma2(
    unsigned long long a, unsigned long long b, unsigned long long c) {
    unsigned long long d;
    asm("fma.rn.f32x2 %0, %1, %2, %3;" : "=l"(d) : "l"(a), "l"(b), "l"(c));
    return d;
}
__device__ __forceinline__ unsigned long long mul2(
    unsigned long long a, unsigned long long b) {
    unsigned long long d;
    asm("mul.rn.f32x2 %0, %1, %2;" : "=l"(d) : "l"(a), "l"(b));
    return d;
}
__device__ __forceinline__ unsigned long long pack2(float x, float y) {
    unsigned long long r;
    asm("mov.b64 %0, {%1, %2};" : "=l"(r) : "f"(x), "f"(y));
    return r;
}
__device__ __forceinline__ float2 unpack2(unsigned long long v) {
    float2 r;
    asm("mov.b64 {%0, %1}, %2;" : "=f"(r.x), "=f"(r.y) : "l"(v));
    return r;
}
__device__ __forceinline__ float ex2(float x) {
    float r;
    asm("ex2.approx.f32 %0, %1;" : "=f"(r) : "f"(x));
    return r;
}
__device__ __forceinline__ void cp16(unsigned int saddr, const void* gptr) {
    asm volatile("cp.async.cg.shared.global [%0], [%1], 16;"
                 :: "r"(saddr), "l"(gptr));
}

// ---------------------------------------------------------------------------
// Split-K GEMM partial: part[kc][r][C] = x[r][k0:k0+128] @ w[k0:k0+128][C]
// ---------------------------------------------------------------------------
__global__ __launch_bounds__(128) void gemm_part_kernel(
    const float* __restrict__ xsrc, const float* __restrict__ w,
    float* __restrict__ part, int C)
{
    __shared__ float xs_t[KCHLEN][36];
    const int c  = blockIdx.x * 128 + threadIdx.x;
    const int k0 = blockIdx.y * KCHLEN;

#pragma unroll 4
    for (int j = 0; j < SQ; j++)
        xs_t[threadIdx.x][j] = xsrc[j * EMB + k0 + threadIdx.x];
    __syncthreads();

    unsigned long long acc[16];
#pragma unroll
    for (int i = 0; i < 16; i++) acc[i] = 0ull;

#pragma unroll 16
    for (int k = 0; k < KCHLEN; k++) {
        const float wv = w[(size_t)(k0 + k) * C + c];
        const unsigned long long w2 = pack2(wv, wv);
#pragma unroll
        for (int r4 = 0; r4 < 8; r4++) {
            const ulonglong2 x4 = *(const ulonglong2*)&xs_t[k][r4 * 4];
            acc[r4 * 2]     = ffma2(x4.x, w2, acc[r4 * 2]);
            acc[r4 * 2 + 1] = ffma2(x4.y, w2, acc[r4 * 2 + 1]);
        }
    }

    float* p = part + (size_t)blockIdx.y * SQ * C + c;
#pragma unroll
    for (int i = 0; i < 16; i++) {
        const float2 v = unpack2(acc[i]);
        p[(size_t)(2 * i)     * C] = v.x;
        p[(size_t)(2 * i + 1) * C] = v.y;
    }
}

// ---------------------------------------------------------------------------
// Reduce qkv partials + bias -> g_qkv ; scatter new K/V rows into present tail
// ---------------------------------------------------------------------------
__global__ __launch_bounds__(256) void reduce_qkv_kernel(
    const float* __restrict__ b, float* __restrict__ dout)
{
    const int c = blockIdx.x * 256 + threadIdx.x;   // 0..3071
    const int r = blockIdx.y;
    float v = b[c];
#pragma unroll
    for (int kc = 0; kc < KCH; kc++)
        v += g_pqkv[((size_t)kc * SQ + r) * (3 * EMB) + c];
    g_qkv[r * 3 * EMB + c] = v;
    if (c >= EMB) {
        const int which = (c >= 2 * EMB) ? 1 : 0;   // 0=K, 1=V
        const int cc = c - EMB - which * EMB;
        const int h = cc / HD, d = cc % HD;
        dout[(size_t)SQ * EMB
             + ((size_t)which * NH + h) * (size_t)TOT * HD
             + (size_t)(PASTN + r) * HD + d] = v;
    }
}

// ---------------------------------------------------------------------------
// Attention: lane = query row, warp = one (head, split).
// cp.async double-buffered 16-key tiles, 3 CTAs/SM. grid (NSPLITS, 4), 128 thr.
// ---------------------------------------------------------------------------
__global__ __launch_bounds__(128, 3) void attn_kernel(
    const float* __restrict__ past, float* __restrict__ dout)
{
    extern __shared__ float smem[];
    const int wid = threadIdx.x >> 5, lane = threadIdx.x & 31;
    const int sp = blockIdx.x;
    const int h  = blockIdx.y * 4 + wid;

    float* Kb = smem + wid * 2048;            // [2][16][64]
    float* Vb = smem + 8192 + wid * 2048;     // [2][16][64]
    const unsigned int KbA = (unsigned int)__cvta_generic_to_shared(Kb);
    const unsigned int VbA = (unsigned int)__cvta_generic_to_shared(Vb);

    const bool isnew = (sp == NSPLITS - 1);
    int t0, tend;
    if (isnew) { t0 = PASTN; tend = TOT; }
    else       { t0 = sp * PCHUNK; tend = min(t0 + PCHUNK, PASTN); }
    const int nt = (tend - t0) >> 4;          // 16-key tiles

    // q for row `lane`, pre-scaled by 1/sqrt(d) * log2(e)
    const float qc = 0.125f * 1.4426950408889634f;
    unsigned long long q2[32];
    {
        const float* qp = g_qkv + lane * 3 * EMB + h * HD;
#pragma unroll
        for (int i = 0; i < 16; i++) {
            const float4 v = *(const float4*)(qp + i * 4);
            q2[2 * i]     = pack2(v.x * qc, v.y * qc);
            q2[2 * i + 1] = pack2(v.z * qc, v.w * qc);
        }
    }

    unsigned long long o2[32];
#pragma unroll
    for (int i = 0; i < 32; i++) o2[i] = 0ull;
    float m = -1e30f, l = 0.f;

    float* presK = dout + SQ * EMB + (size_t)h * TOT * HD;
    float* presV = presK + (size_t)NH * TOT * HD;
    const float* srcK = isnew ? (presK + (size_t)t0 * HD)
                              : (past + ((size_t)h * PASTN + t0) * (size_t)HD);
    const float* srcV = isnew ? (presV + (size_t)t0 * HD)
                              : (past + ((size_t)(NH + h) * PASTN + t0) * (size_t)HD);

    // prefetch tile 0
#pragma unroll
    for (int r = 0; r < 8; r++) {
        const int f4 = r * 32 + lane;
        cp16(KbA + (unsigned)f4 * 16, srcK + (size_t)f4 * 4);
        cp16(VbA + (unsigned)f4 * 16, srcV + (size_t)f4 * 4);
    }
    asm volatile("cp.async.commit_group;");

    for (int i = 0; i < nt; i++) {
        const int buf = i & 1;
        if (i + 1 < nt) {
            const unsigned boff = (unsigned)((i + 1) & 1) * 4096u;
            const size_t gbase = (size_t)(i + 1) * 16 * HD;
#pragma unroll
            for (int r = 0; r < 8; r++) {
                const int f4 = r * 32 + lane;
                cp16(KbA + boff + (unsigned)f4 * 16, srcK + gbase + (size_t)f4 * 4);
                cp16(VbA + boff + (unsigned)f4 * 16, srcV + gbase + (size_t)f4 * 4);
            }
            asm volatile("cp.async.commit_group;");
            asm volatile("cp.async.wait_group 1;");
        } else {
            asm volatile("cp.async.wait_group 0;");
        }
        __syncwarp();

        const float* K = Kb + buf * 1024;
        const float* V = Vb + buf * 1024;
        const int tt = t0 + i * 16;

        // ---- scores for 16 keys (broadcast LDS, 4 accumulator chains) ----
        float s[16];
#pragma unroll
        for (int kk = 0; kk < 16; kk++) {
            unsigned long long a0 = 0ull, a1 = 0ull, a2 = 0ull, a3 = 0ull;
            const float* Kr = K + kk * HD;
#pragma unroll
            for (int ii = 0; ii < 16; ii += 2) {
                const ulonglong2 ka = *(const ulonglong2*)(Kr + ii * 4);
                const ulonglong2 kb = *(const ulonglong2*)(Kr + ii * 4 + 4);
                a0 = ffma2(q2[2 * ii],     ka.x, a0);
                a1 = ffma2(q2[2 * ii + 1], ka.y, a1);
                a2 = ffma2(q2[2 * ii + 2], kb.x, a2);
                a3 = ffma2(q2[2 * ii + 3], kb.y, a3);
            }
            const float2 fa = unpack2(a0), fb = unpack2(a1);
            const float2 fc = unpack2(a2), fd = unpack2(a3);
            s[kk] = ((fa.x + fa.y) + (fb.x + fb.y))
                  + ((fc.x + fc.y) + (fd.x + fd.y));
            if (isnew) {
                if (tt - PASTN + kk > lane) s[kk] = -1e30f;
            }
        }

        // ---- K copy-through (overlaps softmax/PV issue stream) ----
        if (!isnew) {
#pragma unroll
            for (int r = 0; r < 8; r++) {
                const int f4 = r * 32 + lane;
                *(float4*)&presK[(size_t)tt * HD + (size_t)f4 * 4] =
                    *(const float4*)(K + f4 * 4);
            }
        }

        // ---- online softmax update ----
        float tm = s[0];
#pragma unroll
        for (int kk = 1; kk < 16; kk++) tm = fmaxf(tm, s[kk]);
        const float nm = fmaxf(m, tm);
        const float al = ex2(m - nm);
        m = nm;
        float ps = 0.f;
#pragma unroll
        for (int kk = 0; kk < 16; kk++) {
            s[kk] = ex2(s[kk] - nm);
            ps += s[kk];
        }
        l = l * al + ps;
        const unsigned long long al2 = pack2(al, al);
#pragma unroll
        for (int i2 = 0; i2 < 32; i2++) o2[i2] = mul2(o2[i2], al2);

        // ---- PV accumulate ----
#pragma unroll
        for (int kk = 0; kk < 16; kk++) {
            const unsigned long long p2 = pack2(s[kk], s[kk]);
            const float* Vr = V + kk * HD;
#pragma unroll
            for (int ii = 0; ii < 16; ii++) {
                const ulonglong2 v2 = *(const ulonglong2*)(Vr + ii * 4);
                o2[2 * ii]     = ffma2(p2, v2.x, o2[2 * ii]);
                o2[2 * ii + 1] = ffma2(p2, v2.y, o2[2 * ii + 1]);
            }
        }

        // ---- V copy-through ----
        if (!isnew) {
#pragma unroll
            for (int r = 0; r < 8; r++) {
                const int f4 = r * 32 + lane;
                *(float4*)&presV[(size_t)tt * HD + (size_t)f4 * 4] =
                    *(const float4*)(V + f4 * 4);
            }
        }
    }

    // ---- epilogue: per-lane partial (m, l, o) ----
    const int pb = (h * NSPLITS + sp) * SQ + lane;
    float* pop = g_po + (size_t)pb * HD;
#pragma unroll
    for (int i = 0; i < 16; i++) {
        const float2 a = unpack2(o2[2 * i]);
        const float2 b = unpack2(o2[2 * i + 1]);
        float4 v; v.x = a.x; v.y = a.y; v.z = b.x; v.w = b.y;
        *(float4*)&pop[i * 4] = v;
    }
    g_pml[pb * 2]     = m;
    g_pml[pb * 2 + 1] = l;
}

// ---------------------------------------------------------------------------
// Combine split partials -> g_a. grid (NH, SQ), 512 threads:
// 8 split-groups x 64 dims, smem tree-reduce.
// ---------------------------------------------------------------------------
__global__ __launch_bounds__(512) void combine_kernel()
{
    const int h = blockIdx.x, j = blockIdx.y;
    const int d = threadIdx.x & 63, grp = threadIdx.x >> 6;
    __shared__ float sm[NSPAD], sf[NSPAD];
    __shared__ float sO[8][HD], sL[8];

    for (int i = threadIdx.x; i < NSPAD; i += 512)
        sm[i] = (i < NSPLITS) ? g_pml[((h * NSPLITS + i) * SQ + j) * 2] : -1e30f;
    __syncthreads();

    float g0 = -1e30f, g1 = -1e30f, g2 = -1e30f, g3 = -1e30f;
#pragma unroll
    for (int i = 0; i < NSPAD; i += 4) {
        g0 = fmaxf(g0, sm[i]);     g1 = fmaxf(g1, sm[i + 1]);
        g2 = fmaxf(g2, sm[i + 2]); g3 = fmaxf(g3, sm[i + 3]);
    }
    const float gm = fmaxf(fmaxf(g0, g1), fmaxf(g2, g3));
    for (int i = threadIdx.x; i < NSPLITS; i += 512)
        sf[i] = ex2(sm[i] - gm);
    __syncthreads();

    float L = 0.f, o = 0.f;
    for (int i = grp; i < NSPLITS; i += 8) {
        const float f = sf[i];
        const int idx = (h * NSPLITS + i) * SQ + j;
        L = fmaf(g_pml[idx * 2 + 1], f, L);
        o = fmaf(f, g_po[(size_t)idx * HD + d], o);
    }
    sO[grp][d] = o;
    if (d == 0) sL[grp] = L;
    __syncthreads();
    if (grp == 0) {
        float oo = sO[0][d], LL = sL[0];
#pragma unroll
        for (int g = 1; g < 8; g++) { oo += sO[g][d]; LL += sL[g]; }
        g_a[j * EMB + h * HD + d] = oo / LL;
    }
}

// ---------------------------------------------------------------------------
// Reduce proj partials + bias -> d_out[0 : 32*1024)
// ---------------------------------------------------------------------------
__global__ __launch_bounds__(256) void reduce_proj_kernel(
    const float* __restrict__ b, float* __restrict__ dout)
{
    const int c = blockIdx.x * 256 + threadIdx.x;   // 0..1023
    const int r = blockIdx.y;
    float v = b[c];
#pragma unroll
    for (int kc = 0; kc < KCH; kc++)
        v += g_pprj[((size_t)kc * SQ + r) * EMB + c];
    dout[r * EMB + c] = v;
}

// ---------------------------------------------------------------------------
extern "C" void kernel_launch(void* const* d_in, const int* in_sizes, int n_in,
                              void* d_out, int out_size)
{
    const float* x      = (const float*)d_in[0];
    const float* past   = (const float*)d_in[1];
    const float* w_attn = (const float*)d_in[2];
    const float* b_attn = (const float*)d_in[3];
    const float* w_proj = (const float*)d_in[4];
    const float* b_proj = (const float*)d_in[5];
    float* out = (float*)d_out;

    float* pqkv; cudaGetSymbolAddress((void**)&pqkv, g_pqkv);
    float* pprj; cudaGetSymbolAddress((void**)&pprj, g_pprj);
    float* ga;   cudaGetSymbolAddress((void**)&ga,   g_a);

    cudaFuncSetAttribute(attn_kernel,
                         cudaFuncAttributeMaxDynamicSharedMemorySize, 65536);

    gemm_part_kernel  <<<dim3(24, KCH), 128>>>(x, w_attn, pqkv, 3 * EMB);
    reduce_qkv_kernel <<<dim3(12, SQ),  256>>>(b_attn, out);
    attn_kernel       <<<dim3(NSPLITS, 4), 128, 65536>>>(past, out);
    combine_kernel    <<<dim3(NH, SQ),  512>>>();
    gemm_part_kernel  <<<dim3(8, KCH),  128>>>(ga, w_proj, pprj, EMB);
    reduce_proj_kernel<<<dim3(4, SQ),   256>>>(b_proj, out);
}

// round 7
// speedup vs baseline: 1.0587x; 1.0587x over previous
#include <cuda_runtime.h>

#define SQ      32
#define EMB     1024
#define NH      16
#define HD      64
#define PASTN   32768
#define TOT     32800
#define PCHUNK  448
#define NSPLITS 74       // 73 past splits (448 keys, last=512) + 1 new-token split
#define NSPAD   80
#define KCH     8
#define KCHLEN  128

// Scratch (allocation-free rule: __device__ globals)
__device__ float g_qkv [SQ * 3 * EMB];
__device__ float g_po  [NH * NSPLITS * SQ * HD];
__device__ float g_pml [NH * NSPLITS * SQ * 2];
__device__ float g_a   [SQ * EMB];
__device__ float g_pqkv[KCH * SQ * 3 * EMB];
__device__ float g_pprj[KCH * SQ * EMB];

// ------------------------- packed f32x2 helpers ----------------------------
__device__ __forceinline__ unsigned long long ffma2(
    unsigned long long a, unsigned long long b, unsigned long long c) {
    unsigned long long d;
    asm("fma.rn.f32x2 %0, %1, %2, %3;" : "=l"(d) : "l"(a), "l"(b), "l"(c));
    return d;
}
__device__ __forceinline__ unsigned long long add2(
    unsigned long long a, unsigned long long b) {
    unsigned long long d;
    asm("add.rn.f32x2 %0, %1, %2;" : "=l"(d) : "l"(a), "l"(b));
    return d;
}
__device__ __forceinline__ unsigned long long mul2(
    unsigned long long a, unsigned long long b) {
    unsigned long long d;
    asm("mul.rn.f32x2 %0, %1, %2;" : "=l"(d) : "l"(a), "l"(b));
    return d;
}
__device__ __forceinline__ unsigned long long pack2(float x, float y) {
    unsigned long long r;
    asm("mov.b64 %0, {%1, %2};" : "=l"(r) : "f"(x), "f"(y));
    return r;
}
__device__ __forceinline__ float2 unpack2(unsigned long long v) {
    float2 r;
    asm("mov.b64 {%0, %1}, %2;" : "=f"(r.x), "=f"(r.y) : "l"(v));
    return r;
}
__device__ __forceinline__ float ex2(float x) {
    float r;
    asm("ex2.approx.f32 %0, %1;" : "=f"(r) : "f"(x));
    return r;
}
__device__ __forceinline__ void cp16(unsigned int saddr, const void* gptr) {
    asm volatile("cp.async.cg.shared.global [%0], [%1], 16;"
                 :: "r"(saddr), "l"(gptr));
}

// ---------------------------------------------------------------------------
// Split-K GEMM partial: part[kc][r][C] = x[r][k0:k0+128] @ w[k0:k0+128][C]
// ---------------------------------------------------------------------------
__global__ __launch_bounds__(128) void gemm_part_kernel(
    const float* __restrict__ xsrc, const float* __restrict__ w,
    float* __restrict__ part, int C)
{
    __shared__ float xs_t[KCHLEN][36];
    const int c  = blockIdx.x * 128 + threadIdx.x;
    const int k0 = blockIdx.y * KCHLEN;

#pragma unroll 4
    for (int j = 0; j < SQ; j++)
        xs_t[threadIdx.x][j] = xsrc[j * EMB + k0 + threadIdx.x];
    __syncthreads();

    unsigned long long acc[16];
#pragma unroll
    for (int i = 0; i < 16; i++) acc[i] = 0ull;

#pragma unroll 16
    for (int k = 0; k < KCHLEN; k++) {
        const float wv = w[(size_t)(k0 + k) * C + c];
        const unsigned long long w2 = pack2(wv, wv);
#pragma unroll
        for (int r4 = 0; r4 < 8; r4++) {
            const ulonglong2 x4 = *(const ulonglong2*)&xs_t[k][r4 * 4];
            acc[r4 * 2]     = ffma2(x4.x, w2, acc[r4 * 2]);
            acc[r4 * 2 + 1] = ffma2(x4.y, w2, acc[r4 * 2 + 1]);
        }
    }

    float* p = part + (size_t)blockIdx.y * SQ * C + c;
#pragma unroll
    for (int i = 0; i < 16; i++) {
        const float2 v = unpack2(acc[i]);
        p[(size_t)(2 * i)     * C] = v.x;
        p[(size_t)(2 * i + 1) * C] = v.y;
    }
}

// ---------------------------------------------------------------------------
// Reduce qkv partials + bias -> g_qkv ; scatter new K/V rows into present tail
// ---------------------------------------------------------------------------
__global__ __launch_bounds__(256) void reduce_qkv_kernel(
    const float* __restrict__ b, float* __restrict__ dout)
{
    const int c = blockIdx.x * 256 + threadIdx.x;   // 0..3071
    const int r = blockIdx.y;
    float v = b[c];
#pragma unroll
    for (int kc = 0; kc < KCH; kc++)
        v += g_pqkv[((size_t)kc * SQ + r) * (3 * EMB) + c];
    g_qkv[r * 3 * EMB + c] = v;
    if (c >= EMB) {
        const int which = (c >= 2 * EMB) ? 1 : 0;   // 0=K, 1=V
        const int cc = c - EMB - which * EMB;
        const int h = cc / HD, d = cc % HD;
        dout[(size_t)SQ * EMB
             + ((size_t)which * NH + h) * (size_t)TOT * HD
             + (size_t)(PASTN + r) * HD + d] = v;
    }
}

// ---------------------------------------------------------------------------
// Attention: lane = query row; PAIR of warps per head (dim-split 32+32).
// 256 threads = 4 pairs = 4 heads. grid (NSPLITS, 4) = 296 CTAs = 1 wave.
// Dynamic smem per pair: K[2][16][64] + V[2][16][64] + ps[2][16][64] = 24KB.
// ---------------------------------------------------------------------------
__global__ __launch_bounds__(256, 2) void attn_kernel(
    const float* __restrict__ past, float* __restrict__ dout)
{
    extern __shared__ float smem[];
    const int tid  = threadIdx.x;
    const int warp = tid >> 5, lane = tid & 31;
    const int pair = warp >> 1, half = warp & 1;
    const int dh   = half * 32;                    // dim-half base
    const int sp = blockIdx.x;
    const int h  = blockIdx.y * 4 + pair;

    float* Kb = smem + pair * 2048;                // [2][16][64]
    float* Vb = smem + 8192 + pair * 2048;         // [2][16][64]
    float* ps = smem + 16384 + pair * 2048;        // [2][16][64]
    const unsigned int KbA = (unsigned int)__cvta_generic_to_shared(Kb);
    const unsigned int VbA = (unsigned int)__cvta_generic_to_shared(Vb);

    const bool isnew = (sp == NSPLITS - 1);
    int t0, tend;
    if (isnew)            { t0 = PASTN;       tend = TOT; }
    else if (sp == NSPLITS - 2) { t0 = sp * PCHUNK; tend = PASTN; }
    else                  { t0 = sp * PCHUNK; tend = t0 + PCHUNK; }
    const int nt = (tend - t0) >> 4;               // 16-key tiles

    // q-half for row `lane`, pre-scaled by 1/sqrt(d) * log2(e)
    const float qc = 0.125f * 1.4426950408889634f;
    unsigned long long q2[16];
    {
        const float* qp = g_qkv + lane * 3 * EMB + h * HD + dh;
#pragma unroll
        for (int i = 0; i < 8; i++) {
            const float4 v = *(const float4*)(qp + i * 4);
            q2[2 * i]     = pack2(v.x * qc, v.y * qc);
            q2[2 * i + 1] = pack2(v.z * qc, v.w * qc);
        }
    }

    unsigned long long o2[16];
#pragma unroll
    for (int i = 0; i < 16; i++) o2[i] = 0ull;
    float m = -1e30f, l = 0.f;

    float* presK = dout + SQ * EMB + (size_t)h * TOT * HD;
    float* presV = presK + (size_t)NH * TOT * HD;
    const float* srcK = isnew ? (presK + (size_t)t0 * HD)
                              : (past + ((size_t)h * PASTN + t0) * (size_t)HD);
    const float* srcV = isnew ? (presV + (size_t)t0 * HD)
                              : (past + ((size_t)(NH + h) * PASTN + t0) * (size_t)HD);

    // prefetch tile 0: each warp loads ONLY its dim-half of K and V
#pragma unroll
    for (int r = 0; r < 4; r++) {
        const int f4 = r * 32 + lane;              // 0..127
        const int kk = f4 >> 3, dd = (f4 & 7) << 2;
        const unsigned soff = (unsigned)(kk * HD + dh + dd) * 4u;
        const size_t   goff = (size_t)kk * HD + dh + dd;
        cp16(KbA + soff, srcK + goff);
        cp16(VbA + soff, srcV + goff);
    }
    asm volatile("cp.async.commit_group;");

    for (int i = 0; i < nt; i++) {
        const int buf = i & 1;
        if (i + 1 < nt) {
            const unsigned boff = (unsigned)((i + 1) & 1) * 4096u;
            const size_t gbase = (size_t)(i + 1) * 16 * HD;
#pragma unroll
            for (int r = 0; r < 4; r++) {
                const int f4 = r * 32 + lane;
                const int kk = f4 >> 3, dd = (f4 & 7) << 2;
                const unsigned soff = boff + (unsigned)(kk * HD + dh + dd) * 4u;
                const size_t   goff = gbase + (size_t)kk * HD + dh + dd;
                cp16(KbA + soff, srcK + goff);
                cp16(VbA + soff, srcV + goff);
            }
            asm volatile("cp.async.commit_group;");
            asm volatile("cp.async.wait_group 1;");
        } else {
            asm volatile("cp.async.wait_group 0;");
        }
        __syncwarp();

        const float* K = Kb + buf * 1024;
        const float* V = Vb + buf * 1024;
        float* P = ps + buf * 1024;
        const int tt = t0 + i * 16;

        // ---- partial scores over this warp's 32 dims ----
#pragma unroll
        for (int kk = 0; kk < 16; kk++) {
            unsigned long long a0 = 0ull, a1 = 0ull, a2 = 0ull, a3 = 0ull;
            const float* Kr = K + kk * HD + dh;
#pragma unroll
            for (int g = 0; g < 8; g += 2) {
                const ulonglong2 ka = *(const ulonglong2*)(Kr + g * 4);
                const ulonglong2 kb = *(const ulonglong2*)(Kr + g * 4 + 4);
                a0 = ffma2(q2[2 * g],     ka.x, a0);
                a1 = ffma2(q2[2 * g + 1], ka.y, a1);
                a2 = ffma2(q2[2 * g + 2], kb.x, a2);
                a3 = ffma2(q2[2 * g + 3], kb.y, a3);
            }
            const float2 t = unpack2(add2(add2(a0, a1), add2(a2, a3)));
            P[kk * HD + dh + lane] = t.x + t.y;
        }

        // ---- K-half copy-through (overlaps barrier latency) ----
        if (!isnew) {
#pragma unroll
            for (int r = 0; r < 4; r++) {
                const int f4 = r * 32 + lane;
                const int kk = f4 >> 3, dd = (f4 & 7) << 2;
                *(float4*)&presK[(size_t)(tt + kk) * HD + dh + dd] =
                    *(const float4*)(K + kk * HD + dh + dd);
            }
        }

        asm volatile("bar.sync %0, 64;" :: "r"(pair + 1));

        // ---- full scores = own + partner partial; softmax ----
        float s[16];
        const int dother = 32 - dh;
#pragma unroll
        for (int kk = 0; kk < 16; kk++) {
            s[kk] = P[kk * HD + dh + lane] + P[kk * HD + dother + lane];
            if (isnew) {
                if (tt - PASTN + kk > lane) s[kk] = -1e30f;
            }
        }
        float tm = s[0];
#pragma unroll
        for (int kk = 1; kk < 16; kk++) tm = fmaxf(tm, s[kk]);
        const float nm = fmaxf(m, tm);
        const float al = ex2(m - nm);
        m = nm;
        float psum = 0.f;
#pragma unroll
        for (int kk = 0; kk < 16; kk++) {
            s[kk] = ex2(s[kk] - nm);
            psum += s[kk];
        }
        l = l * al + psum;
        const unsigned long long al2 = pack2(al, al);
#pragma unroll
        for (int i2 = 0; i2 < 16; i2++) o2[i2] = mul2(o2[i2], al2);

        // ---- PV accumulate over this warp's 32 dims ----
#pragma unroll
        for (int kk = 0; kk < 16; kk++) {
            const unsigned long long p2 = pack2(s[kk], s[kk]);
            const float* Vr = V + kk * HD + dh;
#pragma unroll
            for (int g = 0; g < 8; g++) {
                const ulonglong2 v2 = *(const ulonglong2*)(Vr + g * 4);
                o2[2 * g]     = ffma2(p2, v2.x, o2[2 * g]);
                o2[2 * g + 1] = ffma2(p2, v2.y, o2[2 * g + 1]);
            }
        }

        // ---- V-half copy-through ----
        if (!isnew) {
#pragma unroll
            for (int r = 0; r < 4; r++) {
                const int f4 = r * 32 + lane;
                const int kk = f4 >> 3, dd = (f4 & 7) << 2;
                *(float4*)&presV[(size_t)(tt + kk) * HD + dh + dd] =
                    *(const float4*)(V + kk * HD + dh + dd);
            }
        }
    }

    // ---- epilogue: per-lane partial (m, l, o-half) ----
    const int pb = (h * NSPLITS + sp) * SQ + lane;
    float* pop = g_po + (size_t)pb * HD + dh;
#pragma unroll
    for (int i = 0; i < 8; i++) {
        const float2 a = unpack2(o2[2 * i]);
        const float2 b = unpack2(o2[2 * i + 1]);
        float4 v; v.x = a.x; v.y = a.y; v.z = b.x; v.w = b.y;
        *(float4*)&pop[i * 4] = v;
    }
    if (half == 0) {
        g_pml[pb * 2]     = m;
        g_pml[pb * 2 + 1] = l;
    }
}

// ---------------------------------------------------------------------------
// Combine split partials -> g_a. grid (NH, SQ), 256 threads:
// 4 split-groups x 64 dims, smem tree-reduce.
// ---------------------------------------------------------------------------
__global__ __launch_bounds__(256) void combine_kernel()
{
    const int h = blockIdx.x, j = blockIdx.y;
    const int d = threadIdx.x & 63, grp = threadIdx.x >> 6;
    __shared__ float sm[NSPAD], sf[NSPAD];
    __shared__ float sO[4][HD], sL[4];

    for (int i = threadIdx.x; i < NSPAD; i += 256)
        sm[i] = (i < NSPLITS) ? g_pml[((h * NSPLITS + i) * SQ + j) * 2] : -1e30f;
    __syncthreads();

    float g0 = -1e30f, g1 = -1e30f, g2 = -1e30f, g3 = -1e30f;
#pragma unroll
    for (int i = 0; i < NSPAD; i += 4) {
        g0 = fmaxf(g0, sm[i]);     g1 = fmaxf(g1, sm[i + 1]);
        g2 = fmaxf(g2, sm[i + 2]); g3 = fmaxf(g3, sm[i + 3]);
    }
    const float gm = fmaxf(fmaxf(g0, g1), fmaxf(g2, g3));
    for (int i = threadIdx.x; i < NSPLITS; i += 256)
        sf[i] = ex2(sm[i] - gm);
    __syncthreads();

    float L = 0.f, o = 0.f;
    for (int i = grp; i < NSPLITS; i += 4) {
        const float f = sf[i];
        const int idx = (h * NSPLITS + i) * SQ + j;
        L = fmaf(g_pml[idx * 2 + 1], f, L);
        o = fmaf(f, g_po[(size_t)idx * HD + d], o);
    }
    sO[grp][d] = o;
    if (d == 0) sL[grp] = L;
    __syncthreads();
    if (grp == 0) {
        const float oo = (sO[0][d] + sO[1][d]) + (sO[2][d] + sO[3][d]);
        const float LL = (sL[0] + sL[1]) + (sL[2] + sL[3]);
        g_a[j * EMB + h * HD + d] = oo / LL;
    }
}

// ---------------------------------------------------------------------------
// Reduce proj partials + bias -> d_out[0 : 32*1024)
// ---------------------------------------------------------------------------
__global__ __launch_bounds__(256) void reduce_proj_kernel(
    const float* __restrict__ b, float* __restrict__ dout)
{
    const int c = blockIdx.x * 256 + threadIdx.x;   // 0..1023
    const int r = blockIdx.y;
    float v = b[c];
#pragma unroll
    for (int kc = 0; kc < KCH; kc++)
        v += g_pprj[((size_t)kc * SQ + r) * EMB + c];
    dout[r * EMB + c] = v;
}

// ---------------------------------------------------------------------------
extern "C" void kernel_launch(void* const* d_in, const int* in_sizes, int n_in,
                              void* d_out, int out_size)
{
    const float* x      = (const float*)d_in[0];
    const float* past   = (const float*)d_in[1];
    const float* w_attn = (const float*)d_in[2];
    const float* b_attn = (const float*)d_in[3];
    const float* w_proj = (const float*)d_in[4];
    const float* b_proj = (const float*)d_in[5];
    float* out = (float*)d_out;

    float* pqkv; cudaGetSymbolAddress((void**)&pqkv, g_pqkv);
    float* pprj; cudaGetSymbolAddress((void**)&pprj, g_pprj);
    float* ga;   cudaGetSymbolAddress((void**)&ga,   g_a);

    cudaFuncSetAttribute(attn_kernel,
                         cudaFuncAttributeMaxDynamicSharedMemorySize, 98304);

    gemm_part_kernel  <<<dim3(24, KCH), 128>>>(x, w_attn, pqkv, 3 * EMB);
    reduce_qkv_kernel <<<dim3(12, SQ),  256>>>(b_attn, out);
    attn_kernel       <<<dim3(NSPLITS, 4), 256, 98304>>>(past, out);
    combine_kernel    <<<dim3(NH, SQ),  256>>>();
    gemm_part_kernel  <<<dim3(8, KCH),  128>>>(ga, w_proj, pprj, EMB);
    reduce_proj_kernel<<<dim3(4, SQ),   256>>>(b_proj, out);
}

// round 8
// speedup vs baseline: 1.6070x; 1.5178x over previous
#include <cuda_runtime.h>

#define SQ      32
#define EMB     1024
#define NH      16
#define HD      64
#define PASTN   32768
#define TOT     32800
#define PCHUNK  448
#define NSPLITS 74       // 73 past splits + 1 new-token split
#define KCH     8
#define KCHLEN  128

// Scratch (allocation-free rule: __device__ globals)
__device__ float g_qkv [SQ * 3 * EMB];
__device__ float g_po  [NH * NSPLITS * SQ * HD];
__device__ float g_pml [NH * NSPLITS * SQ * 2];
__device__ float g_a   [SQ * EMB];
__device__ float g_pqkv[KCH * SQ * 3 * EMB];
__device__ float g_pprj[KCH * SQ * EMB];

// ------------------------- helpers ----------------------------------------
__device__ __forceinline__ unsigned long long ffma2(
    unsigned long long a, unsigned long long b, unsigned long long c) {
    unsigned long long d;
    asm("fma.rn.f32x2 %0, %1, %2, %3;" : "=l"(d) : "l"(a), "l"(b), "l"(c));
    return d;
}
__device__ __forceinline__ unsigned long long pack2(float x, float y) {
    unsigned long long r;
    asm("mov.b64 %0, {%1, %2};" : "=l"(r) : "f"(x), "f"(y));
    return r;
}
__device__ __forceinline__ float2 unpack2(unsigned long long v) {
    float2 r;
    asm("mov.b64 {%0, %1}, %2;" : "=f"(r.x), "=f"(r.y) : "l"(v));
    return r;
}
__device__ __forceinline__ float ex2(float x) {
    float r;
    asm("ex2.approx.f32 %0, %1;" : "=f"(r) : "f"(x));
    return r;
}
__device__ __forceinline__ unsigned f2tf(float f) {
    unsigned u;
    asm("cvt.rna.tf32.f32 %0, %1;" : "=r"(u) : "f"(f));
    return u;
}
__device__ __forceinline__ void cp16(unsigned int saddr, const void* gptr) {
    asm volatile("cp.async.cg.shared.global [%0], [%1], 16;"
                 :: "r"(saddr), "l"(gptr));
}
__device__ __forceinline__ void mma_tf32(
    float* d, const unsigned* a, unsigned b0, unsigned b1) {
    asm volatile(
        "mma.sync.aligned.m16n8k8.row.col.f32.tf32.tf32.f32 "
        "{%0,%1,%2,%3}, {%4,%5,%6,%7}, {%8,%9}, {%0,%1,%2,%3};"
        : "+f"(d[0]), "+f"(d[1]), "+f"(d[2]), "+f"(d[3])
        : "r"(a[0]), "r"(a[1]), "r"(a[2]), "r"(a[3]), "r"(b0), "r"(b1));
}

// ---------------------------------------------------------------------------
// Split-K GEMM partial: part[kc][r][C] = x[r][k0:k0+128] @ w[k0:k0+128][C]
// ---------------------------------------------------------------------------
__global__ __launch_bounds__(128) void gemm_part_kernel(
    const float* __restrict__ xsrc, const float* __restrict__ w,
    float* __restrict__ part, int C)
{
    __shared__ float xs_t[KCHLEN][36];
    const int c  = blockIdx.x * 128 + threadIdx.x;
    const int k0 = blockIdx.y * KCHLEN;

#pragma unroll 4
    for (int j = 0; j < SQ; j++)
        xs_t[threadIdx.x][j] = xsrc[j * EMB + k0 + threadIdx.x];
    __syncthreads();

    unsigned long long acc[16];
#pragma unroll
    for (int i = 0; i < 16; i++) acc[i] = 0ull;

#pragma unroll 16
    for (int k = 0; k < KCHLEN; k++) {
        const float wv = w[(size_t)(k0 + k) * C + c];
        const unsigned long long w2 = pack2(wv, wv);
#pragma unroll
        for (int r4 = 0; r4 < 8; r4++) {
            const ulonglong2 x4 = *(const ulonglong2*)&xs_t[k][r4 * 4];
            acc[r4 * 2]     = ffma2(x4.x, w2, acc[r4 * 2]);
            acc[r4 * 2 + 1] = ffma2(x4.y, w2, acc[r4 * 2 + 1]);
        }
    }

    float* p = part + (size_t)blockIdx.y * SQ * C + c;
#pragma unroll
    for (int i = 0; i < 16; i++) {
        const float2 v = unpack2(acc[i]);
        p[(size_t)(2 * i)     * C] = v.x;
        p[(size_t)(2 * i + 1) * C] = v.y;
    }
}

// ---------------------------------------------------------------------------
// Reduce qkv partials + bias -> g_qkv ; scatter new K/V rows into present tail
// ---------------------------------------------------------------------------
__global__ __launch_bounds__(256) void reduce_qkv_kernel(
    const float* __restrict__ b, float* __restrict__ dout)
{
    const int c = blockIdx.x * 256 + threadIdx.x;   // 0..3071
    const int r = blockIdx.y;
    float v = b[c];
#pragma unroll
    for (int kc = 0; kc < KCH; kc++)
        v += g_pqkv[((size_t)kc * SQ + r) * (3 * EMB) + c];
    g_qkv[r * 3 * EMB + c] = v;
    if (c >= EMB) {
        const int which = (c >= 2 * EMB) ? 1 : 0;   // 0=K, 1=V
        const int cc = c - EMB - which * EMB;
        const int h = cc / HD, d = cc % HD;
        dout[(size_t)SQ * EMB
             + ((size_t)which * NH + h) * (size_t)TOT * HD
             + (size_t)(PASTN + r) * HD + d] = v;
    }
}

// ---------------------------------------------------------------------------
// Attention via mma.sync tf32. CTA = 256 thr = 8 warps = 4 heads x 2 q-halves.
// grid (NSPLITS, 4) = 296 CTAs. Warp: 16 queries x full 64 dims of one head.
// smem: K[4][2][16][68] + V[4][2][16][72] + Ps[8][16][20] = 80 KB.
// ---------------------------------------------------------------------------
#define KPAD 68
#define VPAD 72
#define K_OFF(head, buf) ((head) * 2176 + (buf) * 1088)
#define V_OFF(head, buf) (8704 + (head) * 2304 + (buf) * 1152)
#define P_OFF(warpid)    (17920 + (warpid) * 320)

__global__ __launch_bounds__(256) void attn_kernel(
    const float* __restrict__ past, float* __restrict__ dout)
{
    extern __shared__ float smem[];
    const int warp = threadIdx.x >> 5, lane = threadIdx.x & 31;
    const int head = warp >> 1, whalf = warp & 1;
    const int g = lane >> 2, t = lane & 3;
    const int sp = blockIdx.x;
    const int h  = blockIdx.y * 4 + head;

    const bool isnew = (sp == NSPLITS - 1);
    int t0, tend;
    if (isnew)                  { t0 = PASTN;       tend = TOT; }
    else if (sp == NSPLITS - 2) { t0 = sp * PCHUNK; tend = PASTN; }
    else                        { t0 = sp * PCHUNK; tend = t0 + PCHUNK; }
    const int nt = (tend - t0) >> 4;

    // ---- Q fragments: 8 k-steps x 4 regs (rows qlo=whalf*16+g, qhi=+8) ----
    const int qlo = whalf * 16 + g, qhi = qlo + 8;
    const float qc = 0.125f * 1.4426950408889634f;   // 1/sqrt(d) * log2(e)
    unsigned qf[32];
    {
        const float* qL = g_qkv + qlo * 3 * EMB + h * HD;
        const float* qH = g_qkv + qhi * 3 * EMB + h * HD;
#pragma unroll
        for (int ks = 0; ks < 8; ks++) {
            qf[ks * 4 + 0] = f2tf(qL[ks * 8 + t]     * qc);
            qf[ks * 4 + 1] = f2tf(qH[ks * 8 + t]     * qc);
            qf[ks * 4 + 2] = f2tf(qL[ks * 8 + t + 4] * qc);
            qf[ks * 4 + 3] = f2tf(qH[ks * 8 + t + 4] * qc);
        }
    }

    float of[8][4];
#pragma unroll
    for (int n = 0; n < 8; n++)
#pragma unroll
        for (int r = 0; r < 4; r++) of[n][r] = 0.f;
    float mlo = -1e30f, mhi = -1e30f, llo = 0.f, lhi = 0.f;

    float* presK = dout + SQ * EMB + (size_t)h * TOT * HD;
    float* presV = presK + (size_t)NH * TOT * HD;
    const float* srcK = isnew ? (presK + (size_t)t0 * HD)
                              : (past + ((size_t)h * PASTN + t0) * (size_t)HD);
    const float* srcV = isnew ? (presV + (size_t)t0 * HD)
                              : (past + ((size_t)(NH + h) * PASTN + t0) * (size_t)HD);

    float* Ps = smem + P_OFF(warp);
    const unsigned KsA = (unsigned)__cvta_generic_to_shared(smem);

    // ---- prefetch tile 0 (this warp loads its half of the head's rows) ----
#pragma unroll
    for (int r = 0; r < 4; r++) {
        const int idx = whalf * 128 + r * 32 + lane;   // 0..255 over pair
        const int row = idx >> 4, c4 = idx & 15;
        cp16(KsA + (unsigned)(K_OFF(head, 0) + row * KPAD + c4 * 4) * 4u,
             srcK + row * HD + c4 * 4);
        cp16(KsA + (unsigned)(V_OFF(head, 0) + row * VPAD + c4 * 4) * 4u,
             srcV + row * HD + c4 * 4);
    }
    asm volatile("cp.async.commit_group;");

    for (int i = 0; i < nt; i++) {
        const int buf = i & 1;
        asm volatile("cp.async.wait_group 0;");
        __syncthreads();
        if (i + 1 < nt) {
            const size_t gb = (size_t)(i + 1) * 16 * HD;
            const int bo = buf ^ 1;
#pragma unroll
            for (int r = 0; r < 4; r++) {
                const int idx = whalf * 128 + r * 32 + lane;
                const int row = idx >> 4, c4 = idx & 15;
                cp16(KsA + (unsigned)(K_OFF(head, bo) + row * KPAD + c4 * 4) * 4u,
                     srcK + gb + row * HD + c4 * 4);
                cp16(KsA + (unsigned)(V_OFF(head, bo) + row * VPAD + c4 * 4) * 4u,
                     srcV + gb + row * HD + c4 * 4);
            }
            asm volatile("cp.async.commit_group;");
        }

        const float* Kt = smem + K_OFF(head, buf);
        const float* Vt = smem + V_OFF(head, buf);
        const unsigned* Ku = (const unsigned*)Kt;
        const unsigned* Vu = (const unsigned*)Vt;
        const int tt = t0 + i * 16;

        // ---- QK: 2 n-tiles x 8 k-steps (2 acc chains each) ----
        float s[2][4];
#pragma unroll
        for (int n = 0; n < 2; n++) {
            float ca[4] = {0.f, 0.f, 0.f, 0.f};
            float cb[4] = {0.f, 0.f, 0.f, 0.f};
            const unsigned* Kr = Ku + (n * 8 + g) * KPAD + t;
#pragma unroll
            for (int ks = 0; ks < 4; ks++) {
                mma_tf32(ca, qf + 4 * ks,       Kr[ks * 8],       Kr[ks * 8 + 4]);
                mma_tf32(cb, qf + 4 * (ks + 4), Kr[(ks + 4) * 8], Kr[(ks + 4) * 8 + 4]);
            }
#pragma unroll
            for (int r = 0; r < 4; r++) s[n][r] = ca[r] + cb[r];
        }

        // ---- copy-through to present (from smem, overlaps mma tail) ----
        if (!isnew) {
#pragma unroll
            for (int r = 0; r < 4; r++) {
                const int idx = whalf * 128 + r * 32 + lane;
                const int row = idx >> 4, c4 = idx & 15;
                *(float4*)&presK[(size_t)(tt + row) * HD + c4 * 4] =
                    *(const float4*)(Kt + row * KPAD + c4 * 4);
                *(float4*)&presV[(size_t)(tt + row) * HD + c4 * 4] =
                    *(const float4*)(Vt + row * VPAD + c4 * 4);
            }
        }

        // ---- causal mask (new-token split only) ----
        if (isnew) {
            const int kb = i * 16;
#pragma unroll
            for (int n = 0; n < 2; n++) {
                const int col = n * 8 + 2 * t;
                if (kb + col     > qlo) s[n][0] = -1e30f;
                if (kb + col + 1 > qlo) s[n][1] = -1e30f;
                if (kb + col     > qhi) s[n][2] = -1e30f;
                if (kb + col + 1 > qhi) s[n][3] = -1e30f;
            }
        }

        // ---- online softmax (quad shfl reductions) ----
        float vlo = fmaxf(fmaxf(s[0][0], s[0][1]), fmaxf(s[1][0], s[1][1]));
        float vhi = fmaxf(fmaxf(s[0][2], s[0][3]), fmaxf(s[1][2], s[1][3]));
        vlo = fmaxf(vlo, __shfl_xor_sync(0xffffffffu, vlo, 1));
        vlo = fmaxf(vlo, __shfl_xor_sync(0xffffffffu, vlo, 2));
        vhi = fmaxf(vhi, __shfl_xor_sync(0xffffffffu, vhi, 1));
        vhi = fmaxf(vhi, __shfl_xor_sync(0xffffffffu, vhi, 2));
        const float nmlo = fmaxf(mlo, vlo), nmhi = fmaxf(mhi, vhi);
        const float allo = ex2(mlo - nmlo), alhi = ex2(mhi - nmhi);
        mlo = nmlo; mhi = nmhi;

        float p[2][4];
#pragma unroll
        for (int n = 0; n < 2; n++) {
            p[n][0] = ex2(s[n][0] - nmlo);
            p[n][1] = ex2(s[n][1] - nmlo);
            p[n][2] = ex2(s[n][2] - nmhi);
            p[n][3] = ex2(s[n][3] - nmhi);
        }
        float slo = (p[0][0] + p[0][1]) + (p[1][0] + p[1][1]);
        float shi = (p[0][2] + p[0][3]) + (p[1][2] + p[1][3]);
        slo += __shfl_xor_sync(0xffffffffu, slo, 1);
        slo += __shfl_xor_sync(0xffffffffu, slo, 2);
        shi += __shfl_xor_sync(0xffffffffu, shi, 1);
        shi += __shfl_xor_sync(0xffffffffu, shi, 2);
        llo = llo * allo + slo;
        lhi = lhi * alhi + shi;

#pragma unroll
        for (int n = 0; n < 8; n++) {
            of[n][0] *= allo; of[n][1] *= allo;
            of[n][2] *= alhi; of[n][3] *= alhi;
        }

        // ---- P -> smem (A-fragment relayout) ----
#pragma unroll
        for (int n = 0; n < 2; n++) {
            *(float2*)&Ps[g * 20 + n * 8 + 2 * t]       = make_float2(p[n][0], p[n][1]);
            *(float2*)&Ps[(g + 8) * 20 + n * 8 + 2 * t] = make_float2(p[n][2], p[n][3]);
        }
        __syncwarp();

        // ---- PV: 2 k-steps x 8 n-tiles ----
#pragma unroll
        for (int ks = 0; ks < 2; ks++) {
            unsigned pa[4];
            pa[0] = f2tf(Ps[g * 20 + ks * 8 + t]);
            pa[1] = f2tf(Ps[(g + 8) * 20 + ks * 8 + t]);
            pa[2] = f2tf(Ps[g * 20 + ks * 8 + t + 4]);
            pa[3] = f2tf(Ps[(g + 8) * 20 + ks * 8 + t + 4]);
            const unsigned* V0 = Vu + (ks * 8 + t) * VPAD + g;
            const unsigned* V1 = Vu + (ks * 8 + t + 4) * VPAD + g;
#pragma unroll
            for (int n = 0; n < 8; n++)
                mma_tf32(of[n], pa, V0[n * 8], V1[n * 8]);
        }
        __syncwarp();
    }

    // ---- epilogue ----
    const int pbl = (h * NSPLITS + sp) * SQ + qlo;
    const int pbh = (h * NSPLITS + sp) * SQ + qhi;
#pragma unroll
    for (int n = 0; n < 8; n++) {
        *(float2*)&g_po[(size_t)pbl * HD + n * 8 + 2 * t] = make_float2(of[n][0], of[n][1]);
        *(float2*)&g_po[(size_t)pbh * HD + n * 8 + 2 * t] = make_float2(of[n][2], of[n][3]);
    }
    if (t == 0) {
        g_pml[pbl * 2] = mlo; g_pml[pbl * 2 + 1] = llo;
        g_pml[pbh * 2] = mhi; g_pml[pbh * 2 + 1] = lhi;
    }
}

// ---------------------------------------------------------------------------
// Combine split partials -> g_a. grid (NH, SQ), 256 threads, 4 split-groups.
// ---------------------------------------------------------------------------
__global__ __launch_bounds__(256) void combine_kernel()
{
    const int h = blockIdx.x, j = blockIdx.y;
    const int d = threadIdx.x & 63, grp = threadIdx.x >> 6;
    __shared__ float sm[NSPLITS], sf[NSPLITS];
    __shared__ float sO[4][HD], sL[4];

    for (int i = threadIdx.x; i < NSPLITS; i += 256)
        sm[i] = g_pml[((h * NSPLITS + i) * SQ + j) * 2];
    __syncthreads();

    float gm = -1e30f;
#pragma unroll 2
    for (int i = 0; i < NSPLITS; i++) gm = fmaxf(gm, sm[i]);
    for (int i = threadIdx.x; i < NSPLITS; i += 256)
        sf[i] = ex2(sm[i] - gm);
    __syncthreads();

    float L = 0.f, o = 0.f;
    for (int i = grp; i < NSPLITS; i += 4) {
        const float f = sf[i];
        const int idx = (h * NSPLITS + i) * SQ + j;
        L = fmaf(g_pml[idx * 2 + 1], f, L);
        o = fmaf(f, g_po[(size_t)idx * HD + d], o);
    }
    sO[grp][d] = o;
    if (d == 0) sL[grp] = L;
    __syncthreads();
    if (grp == 0) {
        const float oo = (sO[0][d] + sO[1][d]) + (sO[2][d] + sO[3][d]);
        const float LL = (sL[0] + sL[1]) + (sL[2] + sL[3]);
        g_a[j * EMB + h * HD + d] = oo / LL;
    }
}

// ---------------------------------------------------------------------------
// Reduce proj partials + bias -> d_out[0 : 32*1024)
// ---------------------------------------------------------------------------
__global__ __launch_bounds__(256) void reduce_proj_kernel(
    const float* __restrict__ b, float* __restrict__ dout)
{
    const int c = blockIdx.x * 256 + threadIdx.x;   // 0..1023
    const int r = blockIdx.y;
    float v = b[c];
#pragma unroll
    for (int kc = 0; kc < KCH; kc++)
        v += g_pprj[((size_t)kc * SQ + r) * EMB + c];
    dout[r * EMB + c] = v;
}

// ---------------------------------------------------------------------------
extern "C" void kernel_launch(void* const* d_in, const int* in_sizes, int n_in,
                              void* d_out, int out_size)
{
    const float* x      = (const float*)d_in[0];
    const float* past   = (const float*)d_in[1];
    const float* w_attn = (const float*)d_in[2];
    const float* b_attn = (const float*)d_in[3];
    const float* w_proj = (const float*)d_in[4];
    const float* b_proj = (const float*)d_in[5];
    float* out = (float*)d_out;

    float* pqkv; cudaGetSymbolAddress((void**)&pqkv, g_pqkv);
    float* pprj; cudaGetSymbolAddress((void**)&pprj, g_pprj);
    float* ga;   cudaGetSymbolAddress((void**)&ga,   g_a);

    cudaFuncSetAttribute(attn_kernel,
                         cudaFuncAttributeMaxDynamicSharedMemorySize, 81920);

    gemm_part_kernel  <<<dim3(24, KCH), 128>>>(x, w_attn, pqkv, 3 * EMB);
    reduce_qkv_kernel <<<dim3(12, SQ),  256>>>(b_attn, out);
    attn_kernel       <<<dim3(NSPLITS, 4), 256, 81920>>>(past, out);
    combine_kernel    <<<dim3(NH, SQ),  256>>>();
    gemm_part_kernel  <<<dim3(8, KCH),  128>>>(ga, w_proj, pprj, EMB);
    reduce_proj_kernel<<<dim3(4, SQ),   256>>>(b_proj, out);
}

// round 9
// speedup vs baseline: 1.8113x; 1.1271x over previous
#include <cuda_runtime.h>

#define SQ      32
#define EMB     1024
#define NH      16
#define HD      64
#define PASTN   32768
#define TOT     32800
#define PCHUNK  448
#define NSPLITS 74       // 73 past splits + 1 new-token split
#define KCH     16
#define KCHLEN  64

// Scratch (allocation-free rule: __device__ globals)
__device__ float g_qkv [SQ * 3 * EMB];
__device__ float g_po  [NH * NSPLITS * SQ * HD];
__device__ float g_pml [NH * NSPLITS * SQ * 2];
__device__ float g_a   [SQ * EMB];
__device__ float g_pqkv[KCH * SQ * 3 * EMB];
__device__ float g_pprj[KCH * SQ * EMB];

// ------------------------- helpers ----------------------------------------
__device__ __forceinline__ unsigned long long ffma2(
    unsigned long long a, unsigned long long b, unsigned long long c) {
    unsigned long long d;
    asm("fma.rn.f32x2 %0, %1, %2, %3;" : "=l"(d) : "l"(a), "l"(b), "l"(c));
    return d;
}
__device__ __forceinline__ unsigned long long pack2(float x, float y) {
    unsigned long long r;
    asm("mov.b64 %0, {%1, %2};" : "=l"(r) : "f"(x), "f"(y));
    return r;
}
__device__ __forceinline__ float2 unpack2(unsigned long long v) {
    float2 r;
    asm("mov.b64 {%0, %1}, %2;" : "=f"(r.x), "=f"(r.y) : "l"(v));
    return r;
}
__device__ __forceinline__ float ex2(float x) {
    float r;
    asm("ex2.approx.f32 %0, %1;" : "=f"(r) : "f"(x));
    return r;
}
__device__ __forceinline__ unsigned f2tf(float f) {
    unsigned u;
    asm("cvt.rna.tf32.f32 %0, %1;" : "=r"(u) : "f"(f));
    return u;
}
__device__ __forceinline__ void cp16(unsigned int saddr, const void* gptr) {
    asm volatile("cp.async.cg.shared.global [%0], [%1], 16;"
                 :: "r"(saddr), "l"(gptr));
}
__device__ __forceinline__ void mma_tf32(
    float* d, const unsigned* a, unsigned b0, unsigned b1) {
    asm volatile(
        "mma.sync.aligned.m16n8k8.row.col.f32.tf32.tf32.f32 "
        "{%0,%1,%2,%3}, {%4,%5,%6,%7}, {%8,%9}, {%0,%1,%2,%3};"
        : "+f"(d[0]), "+f"(d[1]), "+f"(d[2]), "+f"(d[3])
        : "r"(a[0]), "r"(a[1]), "r"(a[2]), "r"(a[3]), "r"(b0), "r"(b1));
}

// ---------------------------------------------------------------------------
// Split-K GEMM partial: part[kc][r][C] = x[r][k0:k0+64] @ w[k0:k0+64][C]
// grid (C/128, KCH), block 128.
// ---------------------------------------------------------------------------
__global__ __launch_bounds__(128) void gemm_part_kernel(
    const float* __restrict__ xsrc, const float* __restrict__ w,
    float* __restrict__ part, int C)
{
    __shared__ float xs_t[KCHLEN][36];
    const int c  = blockIdx.x * 128 + threadIdx.x;
    const int k0 = blockIdx.y * KCHLEN;

    // fill transposed x-tile: 64 k x 32 rows; coalesced over k
    {
        const int k = threadIdx.x & 63;
        const int j0 = (threadIdx.x >> 6) * 16;
#pragma unroll
        for (int jj = 0; jj < 16; jj++)
            xs_t[k][j0 + jj] = xsrc[(j0 + jj) * EMB + k0 + k];
    }
    __syncthreads();

    unsigned long long acc[16];
#pragma unroll
    for (int i = 0; i < 16; i++) acc[i] = 0ull;

#pragma unroll 16
    for (int k = 0; k < KCHLEN; k++) {
        const float wv = w[(size_t)(k0 + k) * C + c];
        const unsigned long long w2 = pack2(wv, wv);
#pragma unroll
        for (int r4 = 0; r4 < 8; r4++) {
            const ulonglong2 x4 = *(const ulonglong2*)&xs_t[k][r4 * 4];
            acc[r4 * 2]     = ffma2(x4.x, w2, acc[r4 * 2]);
            acc[r4 * 2 + 1] = ffma2(x4.y, w2, acc[r4 * 2 + 1]);
        }
    }

    float* p = part + (size_t)blockIdx.y * SQ * C + c;
#pragma unroll
    for (int i = 0; i < 16; i++) {
        const float2 v = unpack2(acc[i]);
        p[(size_t)(2 * i)     * C] = v.x;
        p[(size_t)(2 * i + 1) * C] = v.y;
    }
}

// ---------------------------------------------------------------------------
// Reduce qkv partials + bias -> g_qkv ; scatter new K/V rows into present tail
// ---------------------------------------------------------------------------
__global__ __launch_bounds__(256) void reduce_qkv_kernel(
    const float* __restrict__ b, float* __restrict__ dout)
{
    const int c = blockIdx.x * 256 + threadIdx.x;   // 0..3071
    const int r = blockIdx.y;
    float v0 = b[c], v1 = 0.f;
#pragma unroll
    for (int kc = 0; kc < KCH; kc += 2) {
        v0 += g_pqkv[((size_t)kc * SQ + r) * (3 * EMB) + c];
        v1 += g_pqkv[((size_t)(kc + 1) * SQ + r) * (3 * EMB) + c];
    }
    const float v = v0 + v1;
    g_qkv[r * 3 * EMB + c] = v;
    if (c >= EMB) {
        const int which = (c >= 2 * EMB) ? 1 : 0;   // 0=K, 1=V
        const int cc = c - EMB - which * EMB;
        const int h = cc / HD, d = cc % HD;
        dout[(size_t)SQ * EMB
             + ((size_t)which * NH + h) * (size_t)TOT * HD
             + (size_t)(PASTN + r) * HD + d] = v;
    }
}

// ---------------------------------------------------------------------------
// Attention via mma.sync tf32. CTA = 256 thr = 8 warps = 4 heads x 2 q-halves.
// grid (NSPLITS, 4) = 296 CTAs. Per-pair named barriers (heads drift freely).
// smem: K[4][2][16][68] + V[4][2][16][72] + Ps[8][16][20] = 80 KB.
// ---------------------------------------------------------------------------
#define KPAD 68
#define VPAD 72
#define K_OFF(head, buf) ((head) * 2176 + (buf) * 1088)
#define V_OFF(head, buf) (8704 + (head) * 2304 + (buf) * 1152)
#define P_OFF(warpid)    (17920 + (warpid) * 320)

__global__ __launch_bounds__(256) void attn_kernel(
    const float* __restrict__ past, float* __restrict__ dout)
{
    extern __shared__ float smem[];
    const int warp = threadIdx.x >> 5, lane = threadIdx.x & 31;
    const int head = warp >> 1, whalf = warp & 1;
    const int g = lane >> 2, t = lane & 3;
    const int sp = blockIdx.x;
    const int h  = blockIdx.y * 4 + head;

    const bool isnew = (sp == NSPLITS - 1);
    int t0, tend;
    if (isnew)                  { t0 = PASTN;       tend = TOT; }
    else if (sp == NSPLITS - 2) { t0 = sp * PCHUNK; tend = PASTN; }
    else                        { t0 = sp * PCHUNK; tend = t0 + PCHUNK; }
    const int nt = (tend - t0) >> 4;

    // ---- Q fragments: 8 k-steps x 4 regs (rows qlo=whalf*16+g, qhi=+8) ----
    const int qlo = whalf * 16 + g, qhi = qlo + 8;
    const float qc = 0.125f * 1.4426950408889634f;   // 1/sqrt(d) * log2(e)
    unsigned qf[32];
    {
        const float* qL = g_qkv + qlo * 3 * EMB + h * HD;
        const float* qH = g_qkv + qhi * 3 * EMB + h * HD;
#pragma unroll
        for (int ks = 0; ks < 8; ks++) {
            qf[ks * 4 + 0] = f2tf(qL[ks * 8 + t]     * qc);
            qf[ks * 4 + 1] = f2tf(qH[ks * 8 + t]     * qc);
            qf[ks * 4 + 2] = f2tf(qL[ks * 8 + t + 4] * qc);
            qf[ks * 4 + 3] = f2tf(qH[ks * 8 + t + 4] * qc);
        }
    }

    float of[8][4];
#pragma unroll
    for (int n = 0; n < 8; n++)
#pragma unroll
        for (int r = 0; r < 4; r++) of[n][r] = 0.f;
    float mlo = -1e30f, mhi = -1e30f, llo = 0.f, lhi = 0.f;

    float* presK = dout + SQ * EMB + (size_t)h * TOT * HD;
    float* presV = presK + (size_t)NH * TOT * HD;
    const float* srcK = isnew ? (presK + (size_t)t0 * HD)
                              : (past + ((size_t)h * PASTN + t0) * (size_t)HD);
    const float* srcV = isnew ? (presV + (size_t)t0 * HD)
                              : (past + ((size_t)(NH + h) * PASTN + t0) * (size_t)HD);

    float* Ps = smem + P_OFF(warp);
    const unsigned KsA = (unsigned)__cvta_generic_to_shared(smem);

    // ---- prefetch tile 0 (this warp loads its half of the head's rows) ----
#pragma unroll
    for (int r = 0; r < 4; r++) {
        const int idx = whalf * 128 + r * 32 + lane;   // 0..255 over pair
        const int row = idx >> 4, c4 = idx & 15;
        cp16(KsA + (unsigned)(K_OFF(head, 0) + row * KPAD + c4 * 4) * 4u,
             srcK + row * HD + c4 * 4);
        cp16(KsA + (unsigned)(V_OFF(head, 0) + row * VPAD + c4 * 4) * 4u,
             srcV + row * HD + c4 * 4);
    }
    asm volatile("cp.async.commit_group;");

    for (int i = 0; i < nt; i++) {
        const int buf = i & 1;
        asm volatile("cp.async.wait_group 0;");
        // pair barrier: partner's halves of tile i are also in smem, and
        // partner finished compute i-1 -> safe to overwrite buf (i+1)&1.
        asm volatile("bar.sync %0, 64;" :: "r"(head + 1));
        if (i + 1 < nt) {
            const size_t gb = (size_t)(i + 1) * 16 * HD;
            const int bo = buf ^ 1;
#pragma unroll
            for (int r = 0; r < 4; r++) {
                const int idx = whalf * 128 + r * 32 + lane;
                const int row = idx >> 4, c4 = idx & 15;
                cp16(KsA + (unsigned)(K_OFF(head, bo) + row * KPAD + c4 * 4) * 4u,
                     srcK + gb + row * HD + c4 * 4);
                cp16(KsA + (unsigned)(V_OFF(head, bo) + row * VPAD + c4 * 4) * 4u,
                     srcV + gb + row * HD + c4 * 4);
            }
            asm volatile("cp.async.commit_group;");
        }

        const float* Kt = smem + K_OFF(head, buf);
        const float* Vt = smem + V_OFF(head, buf);
        const unsigned* Ku = (const unsigned*)Kt;
        const unsigned* Vu = (const unsigned*)Vt;
        const int tt = t0 + i * 16;

        // ---- QK: 2 n-tiles x 8 k-steps (2 acc chains each) ----
        float s[2][4];
#pragma unroll
        for (int n = 0; n < 2; n++) {
            float ca[4] = {0.f, 0.f, 0.f, 0.f};
            float cb[4] = {0.f, 0.f, 0.f, 0.f};
            const unsigned* Kr = Ku + (n * 8 + g) * KPAD + t;
#pragma unroll
            for (int ks = 0; ks < 4; ks++) {
                mma_tf32(ca, qf + 4 * ks,       Kr[ks * 8],       Kr[ks * 8 + 4]);
                mma_tf32(cb, qf + 4 * (ks + 4), Kr[(ks + 4) * 8], Kr[(ks + 4) * 8 + 4]);
            }
#pragma unroll
            for (int r = 0; r < 4; r++) s[n][r] = ca[r] + cb[r];
        }

        // ---- copy-through to present (from smem, overlaps mma tail) ----
        if (!isnew) {
#pragma unroll
            for (int r = 0; r < 4; r++) {
                const int idx = whalf * 128 + r * 32 + lane;
                const int row = idx >> 4, c4 = idx & 15;
                *(float4*)&presK[(size_t)(tt + row) * HD + c4 * 4] =
                    *(const float4*)(Kt + row * KPAD + c4 * 4);
                *(float4*)&presV[(size_t)(tt + row) * HD + c4 * 4] =
                    *(const float4*)(Vt + row * VPAD + c4 * 4);
            }
        }

        // ---- causal mask (new-token split only) ----
        if (isnew) {
            const int kb = i * 16;
#pragma unroll
            for (int n = 0; n < 2; n++) {
                const int col = n * 8 + 2 * t;
                if (kb + col     > qlo) s[n][0] = -1e30f;
                if (kb + col + 1 > qlo) s[n][1] = -1e30f;
                if (kb + col     > qhi) s[n][2] = -1e30f;
                if (kb + col + 1 > qhi) s[n][3] = -1e30f;
            }
        }

        // ---- online softmax (quad shfl reductions) ----
        float vlo = fmaxf(fmaxf(s[0][0], s[0][1]), fmaxf(s[1][0], s[1][1]));
        float vhi = fmaxf(fmaxf(s[0][2], s[0][3]), fmaxf(s[1][2], s[1][3]));
        vlo = fmaxf(vlo, __shfl_xor_sync(0xffffffffu, vlo, 1));
        vlo = fmaxf(vlo, __shfl_xor_sync(0xffffffffu, vlo, 2));
        vhi = fmaxf(vhi, __shfl_xor_sync(0xffffffffu, vhi, 1));
        vhi = fmaxf(vhi, __shfl_xor_sync(0xffffffffu, vhi, 2));
        const float nmlo = fmaxf(mlo, vlo), nmhi = fmaxf(mhi, vhi);
        const float allo = ex2(mlo - nmlo), alhi = ex2(mhi - nmhi);
        mlo = nmlo; mhi = nmhi;

        float p[2][4];
#pragma unroll
        for (int n = 0; n < 2; n++) {
            p[n][0] = ex2(s[n][0] - nmlo);
            p[n][1] = ex2(s[n][1] - nmlo);
            p[n][2] = ex2(s[n][2] - nmhi);
            p[n][3] = ex2(s[n][3] - nmhi);
        }
        float slo = (p[0][0] + p[0][1]) + (p[1][0] + p[1][1]);
        float shi = (p[0][2] + p[0][3]) + (p[1][2] + p[1][3]);
        slo += __shfl_xor_sync(0xffffffffu, slo, 1);
        slo += __shfl_xor_sync(0xffffffffu, slo, 2);
        shi += __shfl_xor_sync(0xffffffffu, shi, 1);
        shi += __shfl_xor_sync(0xffffffffu, shi, 2);
        llo = llo * allo + slo;
        lhi = lhi * alhi + shi;

#pragma unroll
        for (int n = 0; n < 8; n++) {
            of[n][0] *= allo; of[n][1] *= allo;
            of[n][2] *= alhi; of[n][3] *= alhi;
        }

        // ---- P -> smem (A-fragment relayout) ----
#pragma unroll
        for (int n = 0; n < 2; n++) {
            *(float2*)&Ps[g * 20 + n * 8 + 2 * t]       = make_float2(p[n][0], p[n][1]);
            *(float2*)&Ps[(g + 8) * 20 + n * 8 + 2 * t] = make_float2(p[n][2], p[n][3]);
        }
        __syncwarp();

        // ---- PV: 2 k-steps x 8 n-tiles ----
#pragma unroll
        for (int ks = 0; ks < 2; ks++) {
            unsigned pa[4];
            pa[0] = f2tf(Ps[g * 20 + ks * 8 + t]);
            pa[1] = f2tf(Ps[(g + 8) * 20 + ks * 8 + t]);
            pa[2] = f2tf(Ps[g * 20 + ks * 8 + t + 4]);
            pa[3] = f2tf(Ps[(g + 8) * 20 + ks * 8 + t + 4]);
            const unsigned* V0 = Vu + (ks * 8 + t) * VPAD + g;
            const unsigned* V1 = Vu + (ks * 8 + t + 4) * VPAD + g;
#pragma unroll
            for (int n = 0; n < 8; n++)
                mma_tf32(of[n], pa, V0[n * 8], V1[n * 8]);
        }
        __syncwarp();
    }

    // ---- epilogue ----
    const int pbl = (h * NSPLITS + sp) * SQ + qlo;
    const int pbh = (h * NSPLITS + sp) * SQ + qhi;
#pragma unroll
    for (int n = 0; n < 8; n++) {
        *(float2*)&g_po[(size_t)pbl * HD + n * 8 + 2 * t] = make_float2(of[n][0], of[n][1]);
        *(float2*)&g_po[(size_t)pbh * HD + n * 8 + 2 * t] = make_float2(of[n][2], of[n][3]);
    }
    if (t == 0) {
        g_pml[pbl * 2] = mlo; g_pml[pbl * 2 + 1] = llo;
        g_pml[pbh * 2] = mhi; g_pml[pbh * 2 + 1] = lhi;
    }
}

// ---------------------------------------------------------------------------
// Combine split partials -> g_a. grid (NH, SQ), 256 threads, 4 split-groups.
// ---------------------------------------------------------------------------
__global__ __launch_bounds__(256) void combine_kernel()
{
    const int h = blockIdx.x, j = blockIdx.y;
    const int d = threadIdx.x & 63, grp = threadIdx.x >> 6;
    __shared__ float sm[NSPLITS], sf[NSPLITS];
    __shared__ float sO[4][HD], sL[4];

    for (int i = threadIdx.x; i < NSPLITS; i += 256)
        sm[i] = g_pml[((h * NSPLITS + i) * SQ + j) * 2];
    __syncthreads();

    float gm = -1e30f;
#pragma unroll 2
    for (int i = 0; i < NSPLITS; i++) gm = fmaxf(gm, sm[i]);
    for (int i = threadIdx.x; i < NSPLITS; i += 256)
        sf[i] = ex2(sm[i] - gm);
    __syncthreads();

    float L0 = 0.f, o0 = 0.f, L1 = 0.f, o1 = 0.f;
    int i = grp;
    for (; i + 4 < NSPLITS; i += 8) {
        const float f0 = sf[i], f1 = sf[i + 4];
        const int x0 = (h * NSPLITS + i) * SQ + j;
        const int x1 = (h * NSPLITS + i + 4) * SQ + j;
        L0 = fmaf(g_pml[x0 * 2 + 1], f0, L0);
        o0 = fmaf(f0, g_po[(size_t)x0 * HD + d], o0);
        L1 = fmaf(g_pml[x1 * 2 + 1], f1, L1);
        o1 = fmaf(f1, g_po[(size_t)x1 * HD + d], o1);
    }
    if (i < NSPLITS) {
        const float f0 = sf[i];
        const int x0 = (h * NSPLITS + i) * SQ + j;
        L0 = fmaf(g_pml[x0 * 2 + 1], f0, L0);
        o0 = fmaf(f0, g_po[(size_t)x0 * HD + d], o0);
    }
    sO[grp][d] = o0 + o1;
    if (d == 0) sL[grp] = L0 + L1;
    __syncthreads();
    if (grp == 0) {
        const float oo = (sO[0][d] + sO[1][d]) + (sO[2][d] + sO[3][d]);
        const float LL = (sL[0] + sL[1]) + (sL[2] + sL[3]);
        g_a[j * EMB + h * HD + d] = oo / LL;
    }
}

// ---------------------------------------------------------------------------
// Reduce proj partials + bias -> d_out[0 : 32*1024)
// ---------------------------------------------------------------------------
__global__ __launch_bounds__(256) void reduce_proj_kernel(
    const float* __restrict__ b, float* __restrict__ dout)
{
    const int c = blockIdx.x * 256 + threadIdx.x;   // 0..1023
    const int r = blockIdx.y;
    float v0 = b[c], v1 = 0.f;
#pragma unroll
    for (int kc = 0; kc < KCH; kc += 2) {
        v0 += g_pprj[((size_t)kc * SQ + r) * EMB + c];
        v1 += g_pprj[((size_t)(kc + 1) * SQ + r) * EMB + c];
    }
    dout[r * EMB + c] = v0 + v1;
}

// ---------------------------------------------------------------------------
extern "C" void kernel_launch(void* const* d_in, const int* in_sizes, int n_in,
                              void* d_out, int out_size)
{
    const float* x      = (const float*)d_in[0];
    const float* past   = (const float*)d_in[1];
    const float* w_attn = (const float*)d_in[2];
    const float* b_attn = (const float*)d_in[3];
    const float* w_proj = (const float*)d_in[4];
    const float* b_proj = (const float*)d_in[5];
    float* out = (float*)d_out;

    float* pqkv; cudaGetSymbolAddress((void**)&pqkv, g_pqkv);
    float* pprj; cudaGetSymbolAddress((void**)&pprj, g_pprj);
    float* ga;   cudaGetSymbolAddress((void**)&ga,   g_a);

    cudaFuncSetAttribute(attn_kernel,
                         cudaFuncAttributeMaxDynamicSharedMemorySize, 81920);

    gemm_part_kernel  <<<dim3(24, KCH), 128>>>(x, w_attn, pqkv, 3 * EMB);
    reduce_qkv_kernel <<<dim3(12, SQ),  256>>>(b_attn, out);
    attn_kernel       <<<dim3(NSPLITS, 4), 256, 81920>>>(past, out);
    combine_kernel    <<<dim3(NH, SQ),  256>>>();
    gemm_part_kernel  <<<dim3(8, KCH),  128>>>(ga, w_proj, pprj, EMB);
    reduce_proj_kernel<<<dim3(4, SQ),   256>>>(b_proj, out);
}

// round 11
// speedup vs baseline: 1.8660x; 1.0302x over previous
#include <cuda_runtime.h>

#define SQ      32
#define EMB     1024
#define NH      16
#define HD      64
#define PASTN   32768
#define TOT     32800
#define PCHUNK  448
#define NSPLITS 74       // 73 past splits + 1 new-token split
#define KCH     16
#define KCHLEN  64

// Scratch (allocation-free rule: __device__ globals)
__device__ float g_qkv [SQ * 3 * EMB];
__device__ float g_po  [NH * NSPLITS * SQ * HD];
__device__ float g_pml [NH * NSPLITS * SQ * 2];
__device__ float g_a   [SQ * EMB];
__device__ float g_pqkv[KCH * SQ * 3 * EMB];
__device__ float g_pprj[KCH * SQ * EMB];

// ------------------------- helpers ----------------------------------------
__device__ __forceinline__ unsigned long long ffma2(
    unsigned long long a, unsigned long long b, unsigned long long c) {
    unsigned long long d;
    asm("fma.rn.f32x2 %0, %1, %2, %3;" : "=l"(d) : "l"(a), "l"(b), "l"(c));
    return d;
}
__device__ __forceinline__ unsigned long long pack2(float x, float y) {
    unsigned long long r;
    asm("mov.b64 %0, {%1, %2};" : "=l"(r) : "f"(x), "f"(y));
    return r;
}
__device__ __forceinline__ float2 unpack2(unsigned long long v) {
    float2 r;
    asm("mov.b64 {%0, %1}, %2;" : "=f"(r.x), "=f"(r.y) : "l"(v));
    return r;
}
__device__ __forceinline__ float ex2(float x) {
    float r;
    asm("ex2.approx.f32 %0, %1;" : "=f"(r) : "f"(x));
    return r;
}
__device__ __forceinline__ unsigned f2tf(float f) {
    unsigned u;
    asm("cvt.rna.tf32.f32 %0, %1;" : "=r"(u) : "f"(f));
    return u;
}
__device__ __forceinline__ void cp16(unsigned int saddr, const void* gptr) {
    asm volatile("cp.async.cg.shared.global [%0], [%1], 16;"
                 :: "r"(saddr), "l"(gptr));
}
__device__ __forceinline__ void mma_tf32(
    float* d, const unsigned* a, unsigned b0, unsigned b1) {
    asm volatile(
        "mma.sync.aligned.m16n8k8.row.col.f32.tf32.tf32.f32 "
        "{%0,%1,%2,%3}, {%4,%5,%6,%7}, {%8,%9}, {%0,%1,%2,%3};"
        : "+f"(d[0]), "+f"(d[1]), "+f"(d[2]), "+f"(d[3])
        : "r"(a[0]), "r"(a[1]), "r"(a[2]), "r"(a[3]), "r"(b0), "r"(b1));
}

// ---------------------------------------------------------------------------
// Split-K GEMM partial: part[kc][r][C] = x[r][k0:k0+64] @ w[k0:k0+64][C]
// grid (C/128, KCH), block 128.
// ---------------------------------------------------------------------------
__global__ __launch_bounds__(128) void gemm_part_kernel(
    const float* __restrict__ xsrc, const float* __restrict__ w,
    float* __restrict__ part, int C)
{
    __shared__ float xs_t[KCHLEN][36];
    const int c  = blockIdx.x * 128 + threadIdx.x;
    const int k0 = blockIdx.y * KCHLEN;

    {
        const int k = threadIdx.x & 63;
        const int j0 = (threadIdx.x >> 6) * 16;
#pragma unroll
        for (int jj = 0; jj < 16; jj++)
            xs_t[k][j0 + jj] = xsrc[(j0 + jj) * EMB + k0 + k];
    }
    __syncthreads();

    unsigned long long acc[16];
#pragma unroll
    for (int i = 0; i < 16; i++) acc[i] = 0ull;

#pragma unroll 16
    for (int k = 0; k < KCHLEN; k++) {
        const float wv = w[(size_t)(k0 + k) * C + c];
        const unsigned long long w2 = pack2(wv, wv);
#pragma unroll
        for (int r4 = 0; r4 < 8; r4++) {
            const ulonglong2 x4 = *(const ulonglong2*)&xs_t[k][r4 * 4];
            acc[r4 * 2]     = ffma2(x4.x, w2, acc[r4 * 2]);
            acc[r4 * 2 + 1] = ffma2(x4.y, w2, acc[r4 * 2 + 1]);
        }
    }

    float* p = part + (size_t)blockIdx.y * SQ * C + c;
#pragma unroll
    for (int i = 0; i < 16; i++) {
        const float2 v = unpack2(acc[i]);
        p[(size_t)(2 * i)     * C] = v.x;
        p[(size_t)(2 * i + 1) * C] = v.y;
    }
}

// ---------------------------------------------------------------------------
// Reduce qkv partials + bias -> g_qkv ; scatter new K/V rows into present tail
// ---------------------------------------------------------------------------
__global__ __launch_bounds__(256) void reduce_qkv_kernel(
    const float* __restrict__ b, float* __restrict__ dout)
{
    const int c = blockIdx.x * 256 + threadIdx.x;   // 0..3071
    const int r = blockIdx.y;
    float v0 = b[c], v1 = 0.f;
#pragma unroll
    for (int kc = 0; kc < KCH; kc += 2) {
        v0 += g_pqkv[((size_t)kc * SQ + r) * (3 * EMB) + c];
        v1 += g_pqkv[((size_t)(kc + 1) * SQ + r) * (3 * EMB) + c];
    }
    const float v = v0 + v1;
    g_qkv[r * 3 * EMB + c] = v;
    if (c >= EMB) {
        const int which = (c >= 2 * EMB) ? 1 : 0;   // 0=K, 1=V
        const int cc = c - EMB - which * EMB;
        const int h = cc / HD, d = cc % HD;
        dout[(size_t)SQ * EMB
             + ((size_t)which * NH + h) * (size_t)TOT * HD
             + (size_t)(PASTN + r) * HD + d] = v;
    }
}

// ---------------------------------------------------------------------------
// Attention via mma.sync tf32. CTA = 256 thr = 8 warps = 4 heads x 2 q-halves.
// grid (NSPLITS, 4) = 296 CTAs. Per-pair named barriers.
// SAFE pipeline: wait_group 0 -> pair-bar -> prefetch(i+1) -> compute.
// (Cross-warp smem reads are only valid because BOTH warps' waits precede
//  the shared barrier — do not reorder.)
// smem: K[4][2][16][68] + V[4][2][16][72] + Ps[8][16][20] = 80 KB.
// ---------------------------------------------------------------------------
#define KPAD 68
#define VPAD 72
#define K_OFF(head, buf) ((head) * 2176 + (buf) * 1088)
#define V_OFF(head, buf) (8704 + (head) * 2304 + (buf) * 1152)
#define P_OFF(warpid)    (17920 + (warpid) * 320)

__global__ __launch_bounds__(256) void attn_kernel(
    const float* __restrict__ past, float* __restrict__ dout)
{
    extern __shared__ float smem[];
    const int warp = threadIdx.x >> 5, lane = threadIdx.x & 31;
    const int head = warp >> 1, whalf = warp & 1;
    const int g = lane >> 2, t = lane & 3;
    const int sp = blockIdx.x;
    const int h  = blockIdx.y * 4 + head;

    const bool isnew = (sp == NSPLITS - 1);
    int t0, tend;
    if (isnew)                  { t0 = PASTN;       tend = TOT; }
    else if (sp == NSPLITS - 2) { t0 = sp * PCHUNK; tend = PASTN; }
    else                        { t0 = sp * PCHUNK; tend = t0 + PCHUNK; }
    const int nt = (tend - t0) >> 4;

    // ---- Q fragments: 8 k-steps x 4 regs (rows qlo=whalf*16+g, qhi=+8) ----
    const int qlo = whalf * 16 + g, qhi = qlo + 8;
    const float qc = 0.125f * 1.4426950408889634f;   // 1/sqrt(d) * log2(e)
    unsigned qf[32];
    {
        const float* qL = g_qkv + qlo * 3 * EMB + h * HD;
        const float* qH = g_qkv + qhi * 3 * EMB + h * HD;
#pragma unroll
        for (int ks = 0; ks < 8; ks++) {
            qf[ks * 4 + 0] = f2tf(qL[ks * 8 + t]     * qc);
            qf[ks * 4 + 1] = f2tf(qH[ks * 8 + t]     * qc);
            qf[ks * 4 + 2] = f2tf(qL[ks * 8 + t + 4] * qc);
            qf[ks * 4 + 3] = f2tf(qH[ks * 8 + t + 4] * qc);
        }
    }

    float of[8][4];
#pragma unroll
    for (int n = 0; n < 8; n++)
#pragma unroll
        for (int r = 0; r < 4; r++) of[n][r] = 0.f;
    float mlo = -1e30f, mhi = -1e30f, llo = 0.f, lhi = 0.f;

    float* presK = dout + SQ * EMB + (size_t)h * TOT * HD;
    float* presV = presK + (size_t)NH * TOT * HD;
    const float* srcK = isnew ? (presK + (size_t)t0 * HD)
                              : (past + ((size_t)h * PASTN + t0) * (size_t)HD);
    const float* srcV = isnew ? (presV + (size_t)t0 * HD)
                              : (past + ((size_t)(NH + h) * PASTN + t0) * (size_t)HD);

    float* Ps = smem + P_OFF(warp);
    const unsigned KsA = (unsigned)__cvta_generic_to_shared(smem);

    // ---- prefetch tile 0 (this warp loads its half of the head's rows) ----
#pragma unroll
    for (int r = 0; r < 4; r++) {
        const int idx = whalf * 128 + r * 32 + lane;   // 0..255 over pair
        const int row = idx >> 4, c4 = idx & 15;
        cp16(KsA + (unsigned)(K_OFF(head, 0) + row * KPAD + c4 * 4) * 4u,
             srcK + row * HD + c4 * 4);
        cp16(KsA + (unsigned)(V_OFF(head, 0) + row * VPAD + c4 * 4) * 4u,
             srcV + row * HD + c4 * 4);
    }
    asm volatile("cp.async.commit_group;");

    for (int i = 0; i < nt; i++) {
        const int buf = i & 1;
        // Tile i (K and V, this warp's halves) landed.
        asm volatile("cp.async.wait_group 0;");
        // Pair barrier: partner's halves also landed (its wait precedes its
        // barrier arrival), and partner finished compute i-1 -> the buffer
        // we prefetch into below is free.
        asm volatile("bar.sync %0, 64;" :: "r"(head + 1));

        if (i + 1 < nt) {
            const size_t gb = (size_t)(i + 1) * 16 * HD;
            const int bo = buf ^ 1;
#pragma unroll
            for (int r = 0; r < 4; r++) {
                const int idx = whalf * 128 + r * 32 + lane;
                const int row = idx >> 4, c4 = idx & 15;
                cp16(KsA + (unsigned)(K_OFF(head, bo) + row * KPAD + c4 * 4) * 4u,
                     srcK + gb + row * HD + c4 * 4);
                cp16(KsA + (unsigned)(V_OFF(head, bo) + row * VPAD + c4 * 4) * 4u,
                     srcV + gb + row * HD + c4 * 4);
            }
            asm volatile("cp.async.commit_group;");
        }

        const float* Kt = smem + K_OFF(head, buf);
        const float* Vt = smem + V_OFF(head, buf);
        const unsigned* Ku = (const unsigned*)Kt;
        const unsigned* Vu = (const unsigned*)Vt;
        const int tt = t0 + i * 16;

        // ---- QK: 2 n-tiles x 8 k-steps (2 acc chains each) ----
        float s[2][4];
#pragma unroll
        for (int n = 0; n < 2; n++) {
            float ca[4] = {0.f, 0.f, 0.f, 0.f};
            float cb[4] = {0.f, 0.f, 0.f, 0.f};
            const unsigned* Kr = Ku + (n * 8 + g) * KPAD + t;
#pragma unroll
            for (int ks = 0; ks < 4; ks++) {
                mma_tf32(ca, qf + 4 * ks,       Kr[ks * 8],       Kr[ks * 8 + 4]);
                mma_tf32(cb, qf + 4 * (ks + 4), Kr[(ks + 4) * 8], Kr[(ks + 4) * 8 + 4]);
            }
#pragma unroll
            for (int r = 0; r < 4; r++) s[n][r] = ca[r] + cb[r];
        }

        // ---- K copy-through (streaming stores; data landed pre-barrier) ----
        if (!isnew) {
#pragma unroll
            for (int r = 0; r < 4; r++) {
                const int idx = whalf * 128 + r * 32 + lane;
                const int row = idx >> 4, c4 = idx & 15;
                __stcs((float4*)&presK[(size_t)(tt + row) * HD + c4 * 4],
                       *(const float4*)(Kt + row * KPAD + c4 * 4));
            }
        }

        // ---- causal mask (new-token split only) ----
        if (isnew) {
            const int kb = i * 16;
#pragma unroll
            for (int n = 0; n < 2; n++) {
                const int col = n * 8 + 2 * t;
                if (kb + col     > qlo) s[n][0] = -1e30f;
                if (kb + col + 1 > qlo) s[n][1] = -1e30f;
                if (kb + col     > qhi) s[n][2] = -1e30f;
                if (kb + col + 1 > qhi) s[n][3] = -1e30f;
            }
        }

        // ---- online softmax (quad shfl reductions) ----
        float vlo = fmaxf(fmaxf(s[0][0], s[0][1]), fmaxf(s[1][0], s[1][1]));
        float vhi = fmaxf(fmaxf(s[0][2], s[0][3]), fmaxf(s[1][2], s[1][3]));
        vlo = fmaxf(vlo, __shfl_xor_sync(0xffffffffu, vlo, 1));
        vlo = fmaxf(vlo, __shfl_xor_sync(0xffffffffu, vlo, 2));
        vhi = fmaxf(vhi, __shfl_xor_sync(0xffffffffu, vhi, 1));
        vhi = fmaxf(vhi, __shfl_xor_sync(0xffffffffu, vhi, 2));
        const float nmlo = fmaxf(mlo, vlo), nmhi = fmaxf(mhi, vhi);
        const float allo = ex2(mlo - nmlo), alhi = ex2(mhi - nmhi);
        mlo = nmlo; mhi = nmhi;

        float p[2][4];
#pragma unroll
        for (int n = 0; n < 2; n++) {
            p[n][0] = ex2(s[n][0] - nmlo);
            p[n][1] = ex2(s[n][1] - nmlo);
            p[n][2] = ex2(s[n][2] - nmhi);
            p[n][3] = ex2(s[n][3] - nmhi);
        }
        float slo = (p[0][0] + p[0][1]) + (p[1][0] + p[1][1]);
        float shi = (p[0][2] + p[0][3]) + (p[1][2] + p[1][3]);
        slo += __shfl_xor_sync(0xffffffffu, slo, 1);
        slo += __shfl_xor_sync(0xffffffffu, slo, 2);
        shi += __shfl_xor_sync(0xffffffffu, shi, 1);
        shi += __shfl_xor_sync(0xffffffffu, shi, 2);
        llo = llo * allo + slo;
        lhi = lhi * alhi + shi;

#pragma unroll
        for (int n = 0; n < 8; n++) {
            of[n][0] *= allo; of[n][1] *= allo;
            of[n][2] *= alhi; of[n][3] *= alhi;
        }

        // ---- P -> smem (A-fragment relayout) ----
#pragma unroll
        for (int n = 0; n < 2; n++) {
            *(float2*)&Ps[g * 20 + n * 8 + 2 * t]       = make_float2(p[n][0], p[n][1]);
            *(float2*)&Ps[(g + 8) * 20 + n * 8 + 2 * t] = make_float2(p[n][2], p[n][3]);
        }
        __syncwarp();

        // ---- PV: 2 k-steps x 8 n-tiles ----
#pragma unroll
        for (int ks = 0; ks < 2; ks++) {
            unsigned pa[4];
            pa[0] = f2tf(Ps[g * 20 + ks * 8 + t]);
            pa[1] = f2tf(Ps[(g + 8) * 20 + ks * 8 + t]);
            pa[2] = f2tf(Ps[g * 20 + ks * 8 + t + 4]);
            pa[3] = f2tf(Ps[(g + 8) * 20 + ks * 8 + t + 4]);
            const unsigned* V0 = Vu + (ks * 8 + t) * VPAD + g;
            const unsigned* V1 = Vu + (ks * 8 + t + 4) * VPAD + g;
#pragma unroll
            for (int n = 0; n < 8; n++)
                mma_tf32(of[n], pa, V0[n * 8], V1[n * 8]);
        }

        // ---- V copy-through (streaming stores) ----
        if (!isnew) {
#pragma unroll
            for (int r = 0; r < 4; r++) {
                const int idx = whalf * 128 + r * 32 + lane;
                const int row = idx >> 4, c4 = idx & 15;
                __stcs((float4*)&presV[(size_t)(tt + row) * HD + c4 * 4],
                       *(const float4*)(Vt + row * VPAD + c4 * 4));
            }
        }
        __syncwarp();
    }

    // ---- epilogue ----
    const int pbl = (h * NSPLITS + sp) * SQ + qlo;
    const int pbh = (h * NSPLITS + sp) * SQ + qhi;
#pragma unroll
    for (int n = 0; n < 8; n++) {
        *(float2*)&g_po[(size_t)pbl * HD + n * 8 + 2 * t] = make_float2(of[n][0], of[n][1]);
        *(float2*)&g_po[(size_t)pbh * HD + n * 8 + 2 * t] = make_float2(of[n][2], of[n][3]);
    }
    if (t == 0) {
        g_pml[pbl * 2] = mlo; g_pml[pbl * 2 + 1] = llo;
        g_pml[pbh * 2] = mhi; g_pml[pbh * 2 + 1] = lhi;
    }
}

// ---------------------------------------------------------------------------
// Combine split partials -> g_a. grid (NH, SQ), 256 threads, 4 split-groups.
// m and l both staged through smem (no scattered LDGs in hot loop).
// ---------------------------------------------------------------------------
__global__ __launch_bounds__(256) void combine_kernel()
{
    const int h = blockIdx.x, j = blockIdx.y;
    const int d = threadIdx.x & 63, grp = threadIdx.x >> 6;
    __shared__ float sf[NSPLITS], sl[NSPLITS];
    __shared__ float sO[4][HD], sL[4];

    for (int i = threadIdx.x; i < NSPLITS; i += 256) {
        const int idx = ((h * NSPLITS + i) * SQ + j) * 2;
        sf[i] = g_pml[idx];
        sl[i] = g_pml[idx + 1];
    }
    __syncthreads();

    float gm = -1e30f;
#pragma unroll 2
    for (int i = 0; i < NSPLITS; i++) gm = fmaxf(gm, sf[i]);
    __syncthreads();
    for (int i = threadIdx.x; i < NSPLITS; i += 256)
        sf[i] = ex2(sf[i] - gm);
    __syncthreads();

    float L0 = 0.f, o0 = 0.f, L1 = 0.f, o1 = 0.f;
    int i = grp;
    for (; i + 4 < NSPLITS; i += 8) {
        const float f0 = sf[i], f1 = sf[i + 4];
        const int x0 = (h * NSPLITS + i) * SQ + j;
        const int x1 = (h * NSPLITS + i + 4) * SQ + j;
        L0 = fmaf(sl[i],     f0, L0);
        o0 = fmaf(f0, g_po[(size_t)x0 * HD + d], o0);
        L1 = fmaf(sl[i + 4], f1, L1);
        o1 = fmaf(f1, g_po[(size_t)x1 * HD + d], o1);
    }
    if (i < NSPLITS) {
        const float f0 = sf[i];
        const int x0 = (h * NSPLITS + i) * SQ + j;
        L0 = fmaf(sl[i], f0, L0);
        o0 = fmaf(f0, g_po[(size_t)x0 * HD + d], o0);
    }
    sO[grp][d] = o0 + o1;
    if (d == 0) sL[grp] = L0 + L1;
    __syncthreads();
    if (grp == 0) {
        const float oo = (sO[0][d] + sO[1][d]) + (sO[2][d] + sO[3][d]);
        const float LL = (sL[0] + sL[1]) + (sL[2] + sL[3]);
        g_a[j * EMB + h * HD + d] = oo / LL;
    }
}

// ---------------------------------------------------------------------------
// Reduce proj partials + bias -> d_out[0 : 32*1024)
// ---------------------------------------------------------------------------
__global__ __launch_bounds__(256) void reduce_proj_kernel(
    const float* __restrict__ b, float* __restrict__ dout)
{
    const int c = blockIdx.x * 256 + threadIdx.x;   // 0..1023
    const int r = blockIdx.y;
    float v0 = b[c], v1 = 0.f;
#pragma unroll
    for (int kc = 0; kc < KCH; kc += 2) {
        v0 += g_pprj[((size_t)kc * SQ + r) * EMB + c];
        v1 += g_pprj[((size_t)(kc + 1) * SQ + r) * EMB + c];
    }
    dout[r * EMB + c] = v0 + v1;
}

// ---------------------------------------------------------------------------
extern "C" void kernel_launch(void* const* d_in, const int* in_sizes, int n_in,
                              void* d_out, int out_size)
{
    const float* x      = (const float*)d_in[0];
    const float* past   = (const float*)d_in[1];
    const float* w_attn = (const float*)d_in[2];
    const float* b_attn = (const float*)d_in[3];
    const float* w_proj = (const float*)d_in[4];
    const float* b_proj = (const float*)d_in[5];
    float* out = (float*)d_out;

    float* pqkv; cudaGetSymbolAddress((void**)&pqkv, g_pqkv);
    float* pprj; cudaGetSymbolAddress((void**)&pprj, g_pprj);
    float* ga;   cudaGetSymbolAddress((void**)&ga,   g_a);

    cudaFuncSetAttribute(attn_kernel,
                         cudaFuncAttributeMaxDynamicSharedMemorySize, 81920);

    gemm_part_kernel  <<<dim3(24, KCH), 128>>>(x, w_attn, pqkv, 3 * EMB);
    reduce_qkv_kernel <<<dim3(12, SQ),  256>>>(b_attn, out);
    attn_kernel       <<<dim3(NSPLITS, 4), 256, 81920>>>(past, out);
    combine_kernel    <<<dim3(NH, SQ),  256>>>();
    gemm_part_kernel  <<<dim3(8, KCH),  128>>>(ga, w_proj, pprj, EMB);
    reduce_proj_kernel<<<dim3(4, SQ),   256>>>(b_proj, out);
}